// round 17
// baseline (speedup 1.0000x reference)
#include <cuda_runtime.h>
#include <stdint.h>

#define BB 16
#define CC 19
#define HH 512
#define WW 512
#define HCH 8
#define HROWS (HH/HCH)    // 64
#define NBLOCKS (BB*CC*HCH)   // 2432 blocks; block = (b*CC+c, hch) strip
#define THREADS 128       // 4 warps = 4 w-segments of one 512-wide strip

#define DSTG 6            // smem ring stages = 3 groups x 2 rows
#define B01  0x01010101u

__device__ unsigned char g_tgt8[BB*HH*WW];  // 4 MB scratch (static, allowed)
__device__ double g_acc;                     // zero-init; edge's last block resets
__device__ unsigned g_ticket;

// ---------------------------------------------------------------------------
// prep: detect int64-vs-int32 targets and convert to uint8 (L2-resident for
// the 19x channel reuse). Sampling safe for the SMALLEST possible buffer.
// ---------------------------------------------------------------------------
__global__ void prep_kernel(const unsigned int* __restrict__ t) {
    bool is32 = false;
    #pragma unroll
    for (unsigned k = 0; k < 16; k++) {
        unsigned idx = k * 262139u + 1u;       // max 3,932,086 < 4,194,304
        is32 |= (__ldg(&t[idx | 1u]) != 0u);   // force odd
    }

    const int n4 = BB * HH * WW / 4;
    const uint4* tv = reinterpret_cast<const uint4*>(t);
    for (int i = blockIdx.x * blockDim.x + threadIdx.x; i < n4;
         i += gridDim.x * blockDim.x) {
        uchar4 o;
        if (is32) {
            uint4 v = tv[i];
            o.x = (unsigned char)v.x; o.y = (unsigned char)v.y;
            o.z = (unsigned char)v.z; o.w = (unsigned char)v.w;
        } else {
            uint4 v0 = tv[2 * i];
            uint4 v1 = tv[2 * i + 1];
            o.x = (unsigned char)v0.x; o.y = (unsigned char)v0.z;
            o.z = (unsigned char)v1.x; o.w = (unsigned char)v1.z;
        }
        reinterpret_cast<uchar4*>(g_tgt8)[i] = o;
    }
}

// ---------------------------------------------------------------------------
struct RowD { float a[4], s[4]; unsigned u, v; };

__device__ __forceinline__ float unpack_b(unsigned w, unsigned sel) {
    return __uint_as_float(__byte_perm(w, 0x4B000000u, sel)) - 8388612.0f;
}

__device__ __forceinline__ void emit_row(
    const RowD& P, const RowD& C0, const RowD& N, float& acc0, float& acc1)
{
    unsigned gxt_b = C0.u * 2u + P.u + N.u;
    unsigned gyt_b = (N.v + 0x04040404u) - P.v;
    #pragma unroll
    for (int i = 0; i < 4; i++) {
        float gx  = fmaf(2.f, C0.a[i], P.a[i] + N.a[i]);
        float gy  = N.s[i] - P.s[i];
        float ein = fabsf(gx) + fabsf(gy);
        unsigned sel = 0x7440u + (unsigned)i;
        float etg = fabsf(unpack_b(gxt_b, sel)) + fabsf(unpack_b(gyt_b, sel));
        float d = ein - etg;
        if (i & 1) acc1 = fmaf(d, d, acc1);
        else       acc0 = fmaf(d, d, acc0);
    }
}

#define WAIT_SYNC(N) do { \
    asm volatile("cp.async.wait_group %0;\n" :: "n"(N) : "memory"); \
    __syncthreads(); \
} while (0)

__global__ __launch_bounds__(THREADS, 7)
void edge_kernel(const float* __restrict__ inp, float* __restrict__ out)
{
    __shared__ __align__(16) float sm_f[DSTG * WW];
    __shared__ __align__(4)  unsigned char sm_t[DSTG * WW];

    const int tid = threadIdx.x;
    const int hch = blockIdx.x & (HCH - 1);
    const int t2  = blockIdx.x >> 3;          // b*CC + c, in [0, 304)
    const unsigned c = (unsigned)(t2 % CC);
    const int b = t2 / CC;
    const unsigned cc4 = c * B01;

    const int cidx = tid * 4;                  // 0..508 (block covers full 512)
    const bool lok = (cidx > 0);
    const bool rok = (cidx + 4 < WW);
    const int oL = lok ? cidx - 1 : 0;         // clamped smem column offsets
    const int oR = rok ? cidx + 4 : WW - 1;
    const int h0 = hch * HROWS;

    const float* plane = inp + (size_t)t2 * (HH * WW);
    const unsigned char* tplane = g_tgt8 + (size_t)b * (HH * WW);

    const uint32_t sf  = (uint32_t)__cvta_generic_to_shared(sm_f);
    const uint32_t stt = (uint32_t)__cvta_generic_to_shared(sm_t);

    // Issue group g = local rows {2g, 2g+1} into stages {st0, st0+1}.
    // One commit per call (empty for g>32) keeps wait_group accounting exact.
    auto issue_group = [&](int g, int st0) {
        if (g <= 32) {                         // rows j in [0,65]
            #pragma unroll
            for (int k = 0; k < 2; k++) {
                int row = h0 - 1 + 2 * g + k;  // global row
                int stg = st0 + k;
                if ((unsigned)row < (unsigned)HH) {
                    const float* gs = plane + (size_t)row * WW + cidx;
                    const unsigned char* gt = tplane + (size_t)row * WW + cidx;
                    uint32_t df = sf  + (uint32_t)(stg * (WW * 4) + cidx * 4);
                    uint32_t dt = stt + (uint32_t)(stg * WW + cidx);
                    asm volatile("cp.async.cg.shared.global [%0], [%1], 16;\n"
                                 :: "r"(df), "l"(gs) : "memory");
                    asm volatile("cp.async.ca.shared.global [%0], [%1], 4;\n"
                                 :: "r"(dt), "l"(gt) : "memory");
                } else {                       // block-uniform OOB: zero-fill
                    float4 z = make_float4(0.f, 0.f, 0.f, 0.f);
                    *reinterpret_cast<float4*>(sm_f + stg * WW + cidx) = z;
                    *reinterpret_cast<unsigned*>(sm_t + stg * WW + cidx) = 0xFFFFFFFFu;
                }
            }
        }
        asm volatile("cp.async.commit_group;\n" ::: "memory");
    };

    // Consume ring stage stg -> derived row terms (champion derive).
    auto consume = [&](RowD& d, int stg) {
        const float* srow = sm_f + stg * WW;
        const unsigned char* trow = sm_t + stg * WW;
        float4 xv = *reinterpret_cast<const float4*>(srow + cidx);
        float xl = lok ? srow[oL] : 0.f;       // halos: plain smem reads
        float xr = rok ? srow[oR] : 0.f;
        d.a[0] = xv.y - xl;   d.a[1] = xv.z - xv.x;
        d.a[2] = xv.w - xv.y; d.a[3] = xr - xv.z;
        d.s[0] = fmaf(2.f, xv.x, xl   + xv.y);
        d.s[1] = fmaf(2.f, xv.y, xv.x + xv.z);
        d.s[2] = fmaf(2.f, xv.z, xv.y + xv.w);
        d.s[3] = fmaf(2.f, xv.w, xv.z + xr);

        unsigned t4 = *reinterpret_cast<const unsigned*>(trow + cidx);
        unsigned tl = (unsigned)trow[oL];
        unsigned tr = (unsigned)trow[oR];
        unsigned th = (lok ? tl : 0xFFu) | ((rok ? tr : 0xFFu) << 8);
        unsigned m01 = __vcmpeq4(t4, cc4) & B01;
        unsigned mh  = __vcmpeq4(th, cc4) & 0x00000101u;
        unsigned ml01 = __byte_perm(m01, mh, 0x2104);
        unsigned mr01 = __byte_perm(m01, mh, 0x5321);
        d.u = (mr01 + B01) - ml01;
        d.v = ml01 + mr01 + m01 * 2u;
    };

    float acc0 = 0.f, acc1 = 0.f;
    RowD rA, rB, rC;

    // Prologue: issue groups 0,1,2 (rows 0..5 -> stages 0..5).
    issue_group(0, 0); issue_group(1, 2); issue_group(2, 4);
    WAIT_SYNC(2);                              // g0 complete
    consume(rA, 0);                            // row 0
    consume(rB, 1);                            // row 1

    // Body: 10 macro-iters x 3 phases; phase = wait+sync, issue, 2x(consume+emit).
    // Phase p consumes rows 2p+2,2p+3 (group p+1) and issues group 3+p.
    // wait_group(1): committed g0..g(2+p), need g(p+1) -> allow 1 incomplete.
    // Issue overwrites stages consumed at phase p-1; this phase's sync fences.
    #pragma unroll 1
    for (int m = 0; m < 10; ++m) {
        int g = 3 * m;
        WAIT_SYNC(1); issue_group(3 + g, 0);
        consume(rC, 2); emit_row(rA, rB, rC, acc0, acc1);
        consume(rA, 3); emit_row(rB, rC, rA, acc0, acc1);
        WAIT_SYNC(1); issue_group(4 + g, 2);
        consume(rB, 4); emit_row(rC, rA, rB, acc0, acc1);
        consume(rC, 5); emit_row(rA, rB, rC, acc0, acc1);
        WAIT_SYNC(1); issue_group(5 + g, 4);
        consume(rA, 0); emit_row(rB, rC, rA, acc0, acc1);
        consume(rB, 1); emit_row(rC, rA, rB, acc0, acc1);
    }
    // Epilogue: phases 30,31 (rows 62..65); groups 33,34 are empty commits.
    WAIT_SYNC(1); issue_group(33, 0);
    consume(rC, 2); emit_row(rA, rB, rC, acc0, acc1);
    consume(rA, 3); emit_row(rB, rC, rA, acc0, acc1);
    WAIT_SYNC(1); issue_group(34, 2);
    consume(rB, 4); emit_row(rC, rA, rB, acc0, acc1);
    consume(rC, 5); emit_row(rA, rB, rC, acc0, acc1);

    asm volatile("cp.async.wait_group 0;\n" ::: "memory");  // drain before exit

    // reduce: warp -> block -> global double; last block finalizes + resets.
    float acc = acc0 + acc1;
    #pragma unroll
    for (int o = 16; o; o >>= 1) acc += __shfl_xor_sync(0xffffffffu, acc, o);
    __shared__ float ws[4];
    if ((tid & 31) == 0) ws[tid >> 5] = acc;
    __syncthreads();
    if (tid == 0) {
        double s = 0.0;
        #pragma unroll
        for (int i = 0; i < 4; i++) s += (double)ws[i];
        atomicAdd(&g_acc, s);
        __threadfence();
        unsigned t = atomicAdd(&g_ticket, 1u);
        if (t == (unsigned)(NBLOCKS - 1)) {
            double v = atomicAdd(&g_acc, 0.0);   // ordered read
            out[0] = (float)(v * (1.0 / ((double)BB * HH * WW)));
            g_acc = 0.0;                          // reset for next replay
            g_ticket = 0u;
        }
    }
}

// ---------------------------------------------------------------------------
extern "C" void kernel_launch(void* const* d_in, const int* in_sizes, int n_in,
                              void* d_out, int out_size)
{
    const float* inp;
    const unsigned int* tgt;
    if (in_sizes[0] == BB * CC * HH * WW) {
        inp = (const float*)d_in[0];
        tgt = (const unsigned int*)d_in[1];
    } else {
        inp = (const float*)d_in[1];
        tgt = (const unsigned int*)d_in[0];
    }
    float* out = (float*)d_out;

    prep_kernel<<<1184, 256>>>(tgt);
    edge_kernel<<<NBLOCKS, THREADS>>>(inp, out);
}